// round 14
// baseline (speedup 1.0000x reference)
#include <cuda_runtime.h>
#include <cuda_fp16.h>
#include <cstdint>

#define NF 64
#define OUTF 12
#define N_MAX 50016
#define E_MAX 800000
#define NB_MAX 256          // scan blocks (N <= 65536)

// ------- scratch: __device__ globals only (allocation-free rule) -------
__device__ int     g_is64;                  // edge_index dtype flag
__device__ int     g_cnt   [N_MAX];         // in-degree count, then bucket cursor
__device__ float   g_degw  [N_MAX];         // weighted degree (incl. self loop)
__device__ int     g_rowptr[N_MAX + 1];
__device__ int     g_bsum  [NB_MAX];        // scan block partials
__device__ int2    g_edge  [E_MAX];         // CSR slot: (src, weight-bits)
__device__ __half2 g_hs1   [N_MAX * 32];    // layer-1: dinv[i]*(x @ W1), fp16
__device__ __half2 g_hs2   [N_MAX * 32];    // layer-2: dinv[i]*(h @ W2), fp16

// ---------------------------------------------------------------------------
__global__ void k_init(const unsigned int* __restrict__ w, int n) {
    int i = blockIdx.x * blockDim.x + threadIdx.x;
    if (i < n) { g_cnt[i] = 0; g_degw[i] = 1.0f; }   // 1.0 = self loop
    if (blockIdx.x == 0 && threadIdx.x == 0) {
        int is64 = 1;
        for (int k = 0; k < 64; k++)
            if (w[2 * k + 1] != 0u) { is64 = 0; break; }
        g_is64 = is64;
    }
}

__device__ __forceinline__ int load_idx(const void* ei, long long pos) {
    if (g_is64) return (int)((const long long*)ei)[pos];
    return ((const int*)ei)[pos];
}

__global__ void k_count(const void* __restrict__ ei,
                        const float* __restrict__ ew, int E) {
    int e = blockIdx.x * blockDim.x + threadIdx.x;
    if (e < E) {
        int d = load_idx(ei, (long long)E + e);
        atomicAdd(&g_cnt[d], 1);
        atomicAdd(&g_degw[d], ew[e]);
    }
}

// ---- scan step A: block-local exclusive scan + block aggregates -----------
__global__ void k_scanA(int n) {
    __shared__ int wsum[8];
    __shared__ int wexcl[9];
    int tid = threadIdx.x, lane = tid & 31, wid = tid >> 5;
    int i = blockIdx.x * 256 + tid;
    int v = (i < n) ? g_cnt[i] : 0;
    int x = v;
#pragma unroll
    for (int off = 1; off < 32; off <<= 1) {
        int y = __shfl_up_sync(0xffffffffu, x, off);
        if (lane >= off) x += y;
    }
    if (lane == 31) wsum[wid] = x;
    __syncthreads();
    if (tid == 0) {
        int s = 0;
#pragma unroll
        for (int w = 0; w < 8; w++) { wexcl[w] = s; s += wsum[w]; }
        wexcl[8] = s;
    }
    __syncthreads();
    if (i < n) g_rowptr[i] = wexcl[wid] + x - v;     // block-local exclusive
    if (tid == 0) g_bsum[blockIdx.x] = wexcl[8];
}

// ---------------------------------------------------------------------------
// Fused launch: blocks [0, nb) finish the scan + reset cnt; blocks [nb, ..)
// run the layer-1 GEMM (scalar FFMA — the f32x2 variant measured neutral
// on time while costing occupancy, R13).
// ---------------------------------------------------------------------------
__global__ void k_scanCG(const float* __restrict__ x,
                         const float* __restrict__ W,
                         int n, int nb) {
    __shared__ float Ws[NF * NF];           // used by gemm half
    __shared__ float xs[8][4][NF];
    int tid = threadIdx.x, lane = tid & 31, wid = tid >> 5;

    if (blockIdx.x < nb) {
        // ---- scan finish: excl = sum(bsum[0..bid-1]) ----
        __shared__ int wred[8];
        int bid = blockIdx.x;
        int v = (tid < bid) ? g_bsum[tid] : 0;
#pragma unroll
        for (int off = 16; off >= 1; off >>= 1)
            v += __shfl_xor_sync(0xffffffffu, v, off);
        if (lane == 0) wred[wid] = v;
        __syncthreads();
        if (tid == 0) {
            int s = 0;
#pragma unroll
            for (int w = 0; w < 8; w++) s += wred[w];
            wred[0] = s;
            if (bid == nb - 1) g_rowptr[n] = s + g_bsum[bid];  // total edges
        }
        __syncthreads();
        int excl = wred[0];
        int i = bid * 256 + tid;
        if (i < n) {
            g_rowptr[i] += excl;
            g_cnt[i] = 0;                        // reset bucket cursors
        }
        return;
    }

    // ---- gemm1: g_hs1[i][2l,2l+1] = rsqrt(degw[i]) * (x[i] @ W1)[2l,2l+1] ----
    for (int i = tid; i < NF * NF; i += blockDim.x) Ws[i] = W[i];
    __syncthreads();

    int warp = wid;
    int row0 = ((blockIdx.x - nb) * 8 + warp) * 4;
    if (row0 >= n) return;
    const float2* Ws2 = (const float2*)Ws;

#pragma unroll
    for (int r = 0; r < 4; r++) {
        int row = row0 + r;
        if (row < n) {
            xs[warp][r][lane]      = x[row * NF + lane];
            xs[warp][r][lane + 32] = x[row * NF + lane + 32];
        }
    }
    __syncwarp();

    float acc[4][2] = {};
#pragma unroll
    for (int k = 0; k < NF; k++) {
        float2 wv = Ws2[k * 32 + lane];     // W[k][2l], W[k][2l+1]
#pragma unroll
        for (int r = 0; r < 4; r++) {
            float xv = xs[warp][r][k];
            acc[r][0] = fmaf(xv, wv.x, acc[r][0]);
            acc[r][1] = fmaf(xv, wv.y, acc[r][1]);
        }
    }
#pragma unroll
    for (int r = 0; r < 4; r++) {
        int row = row0 + r;
        if (row < n) {
            float dv = rsqrtf(g_degw[row]);
            g_hs1[row * 32 + lane] =
                __floats2half2_rn(dv * acc[r][0], dv * acc[r][1]);
        }
    }
}

__global__ void k_bucket(const void* __restrict__ ei,
                         const float* __restrict__ ew, int E) {
    int e = blockIdx.x * blockDim.x + threadIdx.x;
    if (e < E) {
        int s = load_idx(ei, e);
        int d = load_idx(ei, (long long)E + e);
        int pos = g_rowptr[d] + atomicAdd(&g_cnt[d], 1);
        int2 p; p.x = s; p.y = __float_as_int(ew[e]);
        g_edge[pos] = p;
    }
}

// ---------------------------------------------------------------------------
// 8-edge batch, predicated: indices clamped to beg (valid), weights zeroed
// for out-of-range slots. All 8 row loads issue independently (MLP 8).
// ---------------------------------------------------------------------------
__device__ __forceinline__ void gather8(const __half2* __restrict__ hs,
                                        int e, int end, int beg, int lane,
                                        float2& a) {
    int   idx[8]; float wv[8];
#pragma unroll
    for (int j = 0; j < 8; j++) {
        int ej = e + j;
        idx[j] = (ej < end) ? ej : beg;
    }
    int2 E[8];
#pragma unroll
    for (int j = 0; j < 8; j++) E[j] = g_edge[idx[j]];
#pragma unroll
    for (int j = 0; j < 8; j++)
        wv[j] = (e + j < end) ? __int_as_float(E[j].y) : 0.f;
    float2 v[8];
#pragma unroll
    for (int j = 0; j < 8; j++)
        v[j] = __half22float2(hs[E[j].x * 32 + lane]);
#pragma unroll
    for (int j = 0; j < 8; j++) {
        a.x = fmaf(wv[j], v[j].x, a.x);
        a.y = fmaf(wv[j], v[j].y, a.y);
    }
}

// ---------------------------------------------------------------------------
// Fused: gather layer 1 -> finalize -> GEMM layer 2 -> scale (fp16 out)
// Persistent grid; warp per node, lane owns features (2l, 2l+1).
// ---------------------------------------------------------------------------
__global__ void k_g1g2(const float* __restrict__ b1,
                       const float* __restrict__ W2, int n) {
    __shared__ float W2s[NF * NF];
    int tid = threadIdx.x;
    for (int i = tid; i < NF * NF; i += blockDim.x) W2s[i] = W2[i];
    __syncthreads();

    int lane = tid & 31;
    int gwarp = (blockIdx.x * blockDim.x + tid) >> 5;
    int nwarps = (gridDim.x * blockDim.x) >> 5;
    float bb0 = b1[2 * lane], bb1 = b1[2 * lane + 1];
    const float2* W2s2 = (const float2*)W2s;

    for (int row = gwarp; row < n; row += nwarps) {
        int beg = g_rowptr[row], end = g_rowptr[row + 1];
        float2 a = __half22float2(g_hs1[row * 32 + lane]);   // self loop (w=1)
        for (int e = beg; e < end; e += 8)
            gather8(g_hs1, e, end, beg, lane, a);
        float dv = rsqrtf(g_degw[row]);
        float h0 = fmaxf(fmaf(dv, a.x, bb0), 0.f);   // feature 2*lane
        float h1 = fmaxf(fmaf(dv, a.y, bb1), 0.f);   // feature 2*lane+1

        // hs2[row][2l,2l+1] = dv * sum_k h[k] * W2[k][2l,2l+1]
        float acc0 = 0.f, acc1 = 0.f;
#pragma unroll
        for (int kk = 0; kk < 32; kk++) {
            float hk0 = __shfl_sync(0xffffffffu, h0, kk);   // feature 2kk
            float hk1 = __shfl_sync(0xffffffffu, h1, kk);   // feature 2kk+1
            float2 wr0 = W2s2[(2 * kk) * 32 + lane];
            float2 wr1 = W2s2[(2 * kk + 1) * 32 + lane];
            acc0 = fmaf(hk0, wr0.x, acc0);  acc1 = fmaf(hk0, wr0.y, acc1);
            acc0 = fmaf(hk1, wr1.x, acc0);  acc1 = fmaf(hk1, wr1.y, acc1);
        }
        g_hs2[row * 32 + lane] = __floats2half2_rn(dv * acc0, dv * acc1);
    }
}

// ---------------------------------------------------------------------------
// Fused: gather layer 2 -> finalize -> FC head
// ---------------------------------------------------------------------------
__global__ void k_g2fc(const float* __restrict__ b2,
                       const float* __restrict__ Wfc,
                       const float* __restrict__ bfc,
                       float* __restrict__ out, int n) {
    int tid = threadIdx.x;
    int lane = tid & 31;
    int gwarp = (blockIdx.x * blockDim.x + tid) >> 5;
    int nwarps = (gridDim.x * blockDim.x) >> 5;

    float bb0 = b2[2 * lane], bb1 = b2[2 * lane + 1];
    float wf0[OUTF], wf1[OUTF];
#pragma unroll
    for (int j = 0; j < OUTF; j++) {
        wf0[j] = Wfc[(2 * lane) * OUTF + j];
        wf1[j] = Wfc[(2 * lane + 1) * OUTF + j];
    }
    float bfs = (lane < OUTF) ? bfc[lane] : 0.f;

    for (int row = gwarp; row < n; row += nwarps) {
        int beg = g_rowptr[row], end = g_rowptr[row + 1];
        float2 a = __half22float2(g_hs2[row * 32 + lane]);   // self loop
        for (int e = beg; e < end; e += 8)
            gather8(g_hs2, e, end, beg, lane, a);
        float dv = rsqrtf(g_degw[row]);
        float h0 = fmaxf(fmaf(dv, a.x, bb0), 0.f);
        float h1 = fmaxf(fmaf(dv, a.y, bb1), 0.f);

        float p[OUTF];
#pragma unroll
        for (int j = 0; j < OUTF; j++)
            p[j] = fmaf(h0, wf0[j], h1 * wf1[j]);
#pragma unroll
        for (int off = 16; off >= 1; off >>= 1)
#pragma unroll
            for (int j = 0; j < OUTF; j++)
                p[j] += __shfl_xor_sync(0xffffffffu, p[j], off);
        if (lane < OUTF)
            out[row * OUTF + lane] = p[lane] + bfs;  // all lanes hold full sums
    }
}

// ---------------------------------------------------------------------------
extern "C" void kernel_launch(void* const* d_in, const int* in_sizes, int n_in,
                              void* d_out, int out_size) {
    const float* x   = (const float*)d_in[0];
    const void*  ei  = d_in[1];                      // int32 OR int64 [2, E]
    const float* ea  = (const float*)d_in[2];        // [E, 1]
    const float* W1  = (const float*)d_in[3];
    const float* b1  = (const float*)d_in[4];
    const float* W2  = (const float*)d_in[5];
    const float* b2  = (const float*)d_in[6];
    const float* Wfc = (const float*)d_in[7];
    const float* bfc = (const float*)d_in[8];
    float* out = (float*)d_out;

    int N = in_sizes[0] / NF;
    int E = in_sizes[1] / 2;

    int nb = (N + 255) / 256;                        // scan blocks (<=256)
    int eb = (E + 255) / 256;
    int gb = (N + 31) / 32;                          // gemm1: 32 rows / block
    int pg = 148 * 8;                                // persistent gather grid
    int need = (N + 7) / 8;
    if (pg > need) pg = need;

    // CSR build (shared by both layers); gemm1 overlapped with scan finish
    k_init  <<<nb, 256>>>((const unsigned int*)ei, N);
    k_count <<<eb, 256>>>(ei, ea, E);
    k_scanA <<<nb, 256>>>(N);
    k_scanCG<<<nb + gb, 256>>>(x, W1, N, nb);
    k_bucket<<<eb, 256>>>(ei, ea, E);

    // Fused gather1+GEMM2, then fused gather2+FC
    k_g1g2<<<pg, 256>>>(b1, W2, N);
    k_g2fc<<<pg, 256>>>(b2, Wfc, bfc, out, N);
}

// round 15
// speedup vs baseline: 1.3124x; 1.3124x over previous
#include <cuda_runtime.h>
#include <cuda_fp16.h>
#include <cstdint>

#define NF 64
#define OUTF 12
#define N_MAX 50016
#define E_MAX 800000
#define NB_MAX 256          // scan blocks (N <= 65536)

// ------- scratch: __device__ globals only (allocation-free rule) -------
__device__ int     g_is64;                  // edge_index dtype flag
__device__ int     g_cnt   [N_MAX];         // in-degree count, then bucket cursor
__device__ float   g_degw  [N_MAX];         // weighted degree (incl. self loop)
__device__ int     g_rowptr[N_MAX + 1];
__device__ int     g_bsum  [NB_MAX];        // scan block partials
__device__ int2    g_edge  [E_MAX];         // CSR slot: (src, w*dinv[src] bits)
__device__ __half2 g_hs1   [N_MAX * 32];    // layer-1: x @ W1 (UNscaled), fp16
__device__ __half2 g_hs2   [N_MAX * 32];    // layer-2: h @ W2 (UNscaled), fp16

// ---------------------------------------------------------------------------
__global__ void k_init(const unsigned int* __restrict__ w, int n) {
    int i = blockIdx.x * blockDim.x + threadIdx.x;
    if (i < n) { g_cnt[i] = 0; g_degw[i] = 1.0f; }   // 1.0 = self loop
    if (blockIdx.x == 0 && threadIdx.x == 0) {
        int is64 = 1;
        for (int k = 0; k < 64; k++)
            if (w[2 * k + 1] != 0u) { is64 = 0; break; }
        g_is64 = is64;
    }
}

__device__ __forceinline__ int load_idx(const void* ei, long long pos) {
    if (g_is64) return (int)((const long long*)ei)[pos];
    return ((const int*)ei)[pos];
}

// ---------------------------------------------------------------------------
// Interleaved fusion: bids with bid%3==0 (and q<gb) run the layer-1 GEMM
// (issue-bound); all other bids run the degree count (latency/atomic-bound).
// Every wave carries both types -> complementary pipe usage on each SM.
// gemm1 is degw-independent: hs1 = fp16(x @ W1), no dinv scaling here.
// ---------------------------------------------------------------------------
__global__ void k_cntgm(const void* __restrict__ ei,
                        const float* __restrict__ ew,
                        const float* __restrict__ x,
                        const float* __restrict__ W,
                        int E, int n, int gb) {
    __shared__ float Ws[NF * NF];
    __shared__ float xs[8][4][NF];
    int tid = threadIdx.x, lane = tid & 31, wid = tid >> 5;
    int bid = blockIdx.x;
    int q = bid / 3, t = bid - q * 3;

    if (!(t == 0 && q < gb)) {
        // ---- count ----
        int cidx = bid - min(gb, q + (t > 0 ? 1 : 0));
        int e = cidx * 256 + tid;
        if (e < E) {
            int d = load_idx(ei, (long long)E + e);
            atomicAdd(&g_cnt[d], 1);
            atomicAdd(&g_degw[d], ew[e]);
        }
        return;
    }

    // ---- gemm1: g_hs1[i][2l,2l+1] = (x[i] @ W1)[2l,2l+1], fp16 ----
    for (int i = tid; i < NF * NF; i += blockDim.x) Ws[i] = W[i];
    __syncthreads();

    int row0 = (q * 8 + wid) * 4;
    if (row0 >= n) return;
    const float2* Ws2 = (const float2*)Ws;

#pragma unroll
    for (int r = 0; r < 4; r++) {
        int row = row0 + r;
        if (row < n) {
            xs[wid][r][lane]      = x[row * NF + lane];
            xs[wid][r][lane + 32] = x[row * NF + lane + 32];
        }
    }
    __syncwarp();

    float acc[4][2] = {};
#pragma unroll
    for (int k = 0; k < NF; k++) {
        float2 wv = Ws2[k * 32 + lane];     // W[k][2l], W[k][2l+1]
#pragma unroll
        for (int r = 0; r < 4; r++) {
            float xv = xs[wid][r][k];
            acc[r][0] = fmaf(xv, wv.x, acc[r][0]);
            acc[r][1] = fmaf(xv, wv.y, acc[r][1]);
        }
    }
#pragma unroll
    for (int r = 0; r < 4; r++) {
        int row = row0 + r;
        if (row < n)
            g_hs1[row * 32 + lane] = __floats2half2_rn(acc[r][0], acc[r][1]);
    }
}

// ---- scan step A: block-local exclusive scan + block aggregates -----------
__global__ void k_scanA(int n) {
    __shared__ int wsum[8];
    __shared__ int wexcl[9];
    int tid = threadIdx.x, lane = tid & 31, wid = tid >> 5;
    int i = blockIdx.x * 256 + tid;
    int v = (i < n) ? g_cnt[i] : 0;
    int x = v;
#pragma unroll
    for (int off = 1; off < 32; off <<= 1) {
        int y = __shfl_up_sync(0xffffffffu, x, off);
        if (lane >= off) x += y;
    }
    if (lane == 31) wsum[wid] = x;
    __syncthreads();
    if (tid == 0) {
        int s = 0;
#pragma unroll
        for (int w = 0; w < 8; w++) { wexcl[w] = s; s += wsum[w]; }
        wexcl[8] = s;
    }
    __syncthreads();
    if (i < n) g_rowptr[i] = wexcl[wid] + x - v;     // block-local exclusive
    if (tid == 0) g_bsum[blockIdx.x] = wexcl[8];
}

// ---- scan finish: block bid adds sum(bsum[0..bid-1]), resets cnt ----------
__global__ void k_scanFin(int n, int nb) {
    __shared__ int wred[8];
    int tid = threadIdx.x, lane = tid & 31, wid = tid >> 5;
    int bid = blockIdx.x;
    int v = (tid < bid) ? g_bsum[tid] : 0;
#pragma unroll
    for (int off = 16; off >= 1; off >>= 1)
        v += __shfl_xor_sync(0xffffffffu, v, off);
    if (lane == 0) wred[wid] = v;
    __syncthreads();
    if (tid == 0) {
        int s = 0;
#pragma unroll
        for (int w = 0; w < 8; w++) s += wred[w];
        wred[0] = s;
        if (bid == nb - 1) g_rowptr[n] = s + g_bsum[bid];  // total edges
    }
    __syncthreads();
    int excl = wred[0];
    int i = bid * 256 + tid;
    if (i < n) {
        g_rowptr[i] += excl;
        g_cnt[i] = 0;                                // reset bucket cursors
    }
}

// bucket: store pre-scaled weight w*dinv[src] (degw complete by now)
__global__ void k_bucket(const void* __restrict__ ei,
                         const float* __restrict__ ew, int E) {
    int e = blockIdx.x * blockDim.x + threadIdx.x;
    if (e < E) {
        int s = load_idx(ei, e);
        int d = load_idx(ei, (long long)E + e);
        float ws = ew[e] * rsqrtf(g_degw[s]);
        int pos = g_rowptr[d] + atomicAdd(&g_cnt[d], 1);
        int2 p; p.x = s; p.y = __float_as_int(ws);
        g_edge[pos] = p;
    }
}

// ---------------------------------------------------------------------------
// Fused: gather layer 1 -> finalize -> GEMM layer 2 (fp16 out, unscaled)
// out = relu( dv*(dv*hs_self + sum w~*hs[s]) + b ), w~ = w*dinv[src].
// Persistent grid; warp per node, lane owns features (2l, 2l+1).
// ---------------------------------------------------------------------------
__global__ void k_g1g2(const float* __restrict__ b1,
                       const float* __restrict__ W2, int n) {
    __shared__ float W2s[NF * NF];
    int tid = threadIdx.x;
    for (int i = tid; i < NF * NF; i += blockDim.x) W2s[i] = W2[i];
    __syncthreads();

    int lane = tid & 31;
    int gwarp = (blockIdx.x * blockDim.x + tid) >> 5;
    int nwarps = (gridDim.x * blockDim.x) >> 5;
    float bb0 = b1[2 * lane], bb1 = b1[2 * lane + 1];
    const float2* W2s2 = (const float2*)W2s;

    for (int row = gwarp; row < n; row += nwarps) {
        int beg = g_rowptr[row], end = g_rowptr[row + 1];
        float dv = rsqrtf(g_degw[row]);
        float2 sf = __half22float2(g_hs1[row * 32 + lane]);
        float2 a; a.x = dv * sf.x; a.y = dv * sf.y;          // self loop
        int e = beg;
        for (; e + 7 < end; e += 8) {
            int2 E0 = g_edge[e],   E1 = g_edge[e+1], E2 = g_edge[e+2], E3 = g_edge[e+3];
            int2 E4 = g_edge[e+4], E5 = g_edge[e+5], E6 = g_edge[e+6], E7 = g_edge[e+7];
            float2 v0 = __half22float2(g_hs1[E0.x * 32 + lane]);
            float2 v1 = __half22float2(g_hs1[E1.x * 32 + lane]);
            float2 v2 = __half22float2(g_hs1[E2.x * 32 + lane]);
            float2 v3 = __half22float2(g_hs1[E3.x * 32 + lane]);
            float2 v4 = __half22float2(g_hs1[E4.x * 32 + lane]);
            float2 v5 = __half22float2(g_hs1[E5.x * 32 + lane]);
            float2 v6 = __half22float2(g_hs1[E6.x * 32 + lane]);
            float2 v7 = __half22float2(g_hs1[E7.x * 32 + lane]);
            float w0 = __int_as_float(E0.y), w1 = __int_as_float(E1.y);
            float w2 = __int_as_float(E2.y), w3 = __int_as_float(E3.y);
            float w4 = __int_as_float(E4.y), w5 = __int_as_float(E5.y);
            float w6 = __int_as_float(E6.y), w7 = __int_as_float(E7.y);
            a.x = fmaf(w0, v0.x, a.x);  a.y = fmaf(w0, v0.y, a.y);
            a.x = fmaf(w1, v1.x, a.x);  a.y = fmaf(w1, v1.y, a.y);
            a.x = fmaf(w2, v2.x, a.x);  a.y = fmaf(w2, v2.y, a.y);
            a.x = fmaf(w3, v3.x, a.x);  a.y = fmaf(w3, v3.y, a.y);
            a.x = fmaf(w4, v4.x, a.x);  a.y = fmaf(w4, v4.y, a.y);
            a.x = fmaf(w5, v5.x, a.x);  a.y = fmaf(w5, v5.y, a.y);
            a.x = fmaf(w6, v6.x, a.x);  a.y = fmaf(w6, v6.y, a.y);
            a.x = fmaf(w7, v7.x, a.x);  a.y = fmaf(w7, v7.y, a.y);
        }
        for (; e < end; e++) {
            int2 E0 = g_edge[e];
            float2 v = __half22float2(g_hs1[E0.x * 32 + lane]);
            float w = __int_as_float(E0.y);
            a.x = fmaf(w, v.x, a.x);  a.y = fmaf(w, v.y, a.y);
        }
        float h0 = fmaxf(fmaf(dv, a.x, bb0), 0.f);   // feature 2*lane
        float h1 = fmaxf(fmaf(dv, a.y, bb1), 0.f);   // feature 2*lane+1

        // hs2[row][2l,2l+1] = sum_k h[k] * W2[k][2l,2l+1]  (unscaled)
        float acc0 = 0.f, acc1 = 0.f;
#pragma unroll
        for (int kk = 0; kk < 32; kk++) {
            float hk0 = __shfl_sync(0xffffffffu, h0, kk);   // feature 2kk
            float hk1 = __shfl_sync(0xffffffffu, h1, kk);   // feature 2kk+1
            float2 wr0 = W2s2[(2 * kk) * 32 + lane];
            float2 wr1 = W2s2[(2 * kk + 1) * 32 + lane];
            acc0 = fmaf(hk0, wr0.x, acc0);  acc1 = fmaf(hk0, wr0.y, acc1);
            acc0 = fmaf(hk1, wr1.x, acc0);  acc1 = fmaf(hk1, wr1.y, acc1);
        }
        g_hs2[row * 32 + lane] = __floats2half2_rn(acc0, acc1);
    }
}

// ---------------------------------------------------------------------------
// Fused: gather layer 2 -> finalize -> FC head
// ---------------------------------------------------------------------------
__global__ void k_g2fc(const float* __restrict__ b2,
                       const float* __restrict__ Wfc,
                       const float* __restrict__ bfc,
                       float* __restrict__ out, int n) {
    int tid = threadIdx.x;
    int lane = tid & 31;
    int gwarp = (blockIdx.x * blockDim.x + tid) >> 5;
    int nwarps = (gridDim.x * blockDim.x) >> 5;

    float bb0 = b2[2 * lane], bb1 = b2[2 * lane + 1];
    float wf0[OUTF], wf1[OUTF];
#pragma unroll
    for (int j = 0; j < OUTF; j++) {
        wf0[j] = Wfc[(2 * lane) * OUTF + j];
        wf1[j] = Wfc[(2 * lane + 1) * OUTF + j];
    }
    float bfs = (lane < OUTF) ? bfc[lane] : 0.f;

    for (int row = gwarp; row < n; row += nwarps) {
        int beg = g_rowptr[row], end = g_rowptr[row + 1];
        float dv = rsqrtf(g_degw[row]);
        float2 sf = __half22float2(g_hs2[row * 32 + lane]);
        float2 a; a.x = dv * sf.x; a.y = dv * sf.y;          // self loop
        int e = beg;
        for (; e + 7 < end; e += 8) {
            int2 E0 = g_edge[e],   E1 = g_edge[e+1], E2 = g_edge[e+2], E3 = g_edge[e+3];
            int2 E4 = g_edge[e+4], E5 = g_edge[e+5], E6 = g_edge[e+6], E7 = g_edge[e+7];
            float2 v0 = __half22float2(g_hs2[E0.x * 32 + lane]);
            float2 v1 = __half22float2(g_hs2[E1.x * 32 + lane]);
            float2 v2 = __half22float2(g_hs2[E2.x * 32 + lane]);
            float2 v3 = __half22float2(g_hs2[E3.x * 32 + lane]);
            float2 v4 = __half22float2(g_hs2[E4.x * 32 + lane]);
            float2 v5 = __half22float2(g_hs2[E5.x * 32 + lane]);
            float2 v6 = __half22float2(g_hs2[E6.x * 32 + lane]);
            float2 v7 = __half22float2(g_hs2[E7.x * 32 + lane]);
            float w0 = __int_as_float(E0.y), w1 = __int_as_float(E1.y);
            float w2 = __int_as_float(E2.y), w3 = __int_as_float(E3.y);
            float w4 = __int_as_float(E4.y), w5 = __int_as_float(E5.y);
            float w6 = __int_as_float(E6.y), w7 = __int_as_float(E7.y);
            a.x = fmaf(w0, v0.x, a.x);  a.y = fmaf(w0, v0.y, a.y);
            a.x = fmaf(w1, v1.x, a.x);  a.y = fmaf(w1, v1.y, a.y);
            a.x = fmaf(w2, v2.x, a.x);  a.y = fmaf(w2, v2.y, a.y);
            a.x = fmaf(w3, v3.x, a.x);  a.y = fmaf(w3, v3.y, a.y);
            a.x = fmaf(w4, v4.x, a.x);  a.y = fmaf(w4, v4.y, a.y);
            a.x = fmaf(w5, v5.x, a.x);  a.y = fmaf(w5, v5.y, a.y);
            a.x = fmaf(w6, v6.x, a.x);  a.y = fmaf(w6, v6.y, a.y);
            a.x = fmaf(w7, v7.x, a.x);  a.y = fmaf(w7, v7.y, a.y);
        }
        for (; e < end; e++) {
            int2 E0 = g_edge[e];
            float2 v = __half22float2(g_hs2[E0.x * 32 + lane]);
            float w = __int_as_float(E0.y);
            a.x = fmaf(w, v.x, a.x);  a.y = fmaf(w, v.y, a.y);
        }
        float h0 = fmaxf(fmaf(dv, a.x, bb0), 0.f);
        float h1 = fmaxf(fmaf(dv, a.y, bb1), 0.f);

        float p[OUTF];
#pragma unroll
        for (int j = 0; j < OUTF; j++)
            p[j] = fmaf(h0, wf0[j], h1 * wf1[j]);
#pragma unroll
        for (int off = 16; off >= 1; off >>= 1)
#pragma unroll
            for (int j = 0; j < OUTF; j++)
                p[j] += __shfl_xor_sync(0xffffffffu, p[j], off);
        if (lane < OUTF)
            out[row * OUTF + lane] = p[lane] + bfs;  // all lanes hold full sums
    }
}

// ---------------------------------------------------------------------------
extern "C" void kernel_launch(void* const* d_in, const int* in_sizes, int n_in,
                              void* d_out, int out_size) {
    const float* x   = (const float*)d_in[0];
    const void*  ei  = d_in[1];                      // int32 OR int64 [2, E]
    const float* ea  = (const float*)d_in[2];        // [E, 1]
    const float* W1  = (const float*)d_in[3];
    const float* b1  = (const float*)d_in[4];
    const float* W2  = (const float*)d_in[5];
    const float* b2  = (const float*)d_in[6];
    const float* Wfc = (const float*)d_in[7];
    const float* bfc = (const float*)d_in[8];
    float* out = (float*)d_out;

    int N = in_sizes[0] / NF;
    int E = in_sizes[1] / 2;

    int nb = (N + 255) / 256;                        // scan blocks (<=256)
    int eb = (E + 255) / 256;
    int gb = (N + 31) / 32;                          // gemm1: 32 rows / block
    int pg = 148 * 8;                                // persistent gather grid
    int need = (N + 7) / 8;
    if (pg > need) pg = need;

    // CSR build; count interleaved with gemm1 in one launch
    k_init   <<<nb, 256>>>((const unsigned int*)ei, N);
    k_cntgm  <<<gb + eb, 256>>>(ei, ea, x, W1, E, N, gb);
    k_scanA  <<<nb, 256>>>(N);
    k_scanFin<<<nb, 256>>>(N, nb);
    k_bucket <<<eb, 256>>>(ei, ea, E);

    // Fused gather1+GEMM2, then fused gather2+FC
    k_g1g2<<<pg, 256>>>(b1, W2, N);
    k_g2fc<<<pg, 256>>>(b2, Wfc, bfc, out, N);
}